// round 4
// baseline (speedup 1.0000x reference)
#include <cuda_runtime.h>

#define NN 100000
#define NE 1600000

// Scratch slots, each NN*64 floats (25.6MB): 0..3
__device__ float g_scratch[4ull * NN * 64];
__device__ float g_deg[NN];
__device__ float g_dinv[NN];
__device__ int g_src[NE];
__device__ int g_dst[NE];
__device__ int g_is64;

// A_j = sum_s COEF[s][j] * Wm1_s  (THETAS for D=2 folded)
__constant__ float COEF[3][3] = {
    {3.0f,  0.0f,  0.0f},
    {-3.0f, 3.0f,  0.0f},
    {0.75f, -1.5f, 0.75f}
};

__device__ __forceinline__ float* slot(int s) {
    return g_scratch + (size_t)s * (NN * 64);
}

__device__ __forceinline__ unsigned long long fma2(
    unsigned long long a, unsigned long long b, unsigned long long c) {
    unsigned long long d;
    asm("fma.rn.f32x2 %0, %1, %2, %3;" : "=l"(d) : "l"(a), "l"(b), "l"(c));
    return d;
}

__device__ __forceinline__ float2 unpack2(unsigned long long v) {
    float2 f;
    asm("mov.b64 {%0, %1}, %2;" : "=f"(f.x), "=f"(f.y) : "l"(v));
    return f;
}

// ---------------------------------------------------------------------------
__global__ void zero_detect_kernel(const void* ei) {
    int i = blockIdx.x * 256 + threadIdx.x;
    if (i < NN) g_deg[i] = 0.0f;
    if (i == 0) {
        const unsigned long long* p = (const unsigned long long*)ei;
        int is64 = 1;
        for (int k = 0; k < 64; k++)
            if ((p[k] >> 32) != 0ull) { is64 = 0; break; }
        g_is64 = is64;
    }
}

__global__ void convert_kernel(const void* ei) {
    int e = blockIdx.x * 256 + threadIdx.x;
    if (e < NE) {
        if (g_is64) {
            const long long* p = (const long long*)ei;
            g_src[e] = (int)p[e];
            g_dst[e] = (int)p[NE + e];
        } else {
            const int* p = (const int*)ei;
            g_src[e] = p[e];
            g_dst[e] = p[NE + e];
        }
    }
}

__global__ void count_kernel() {
    int e = blockIdx.x * 256 + threadIdx.x;
    if (e < NE) atomicAdd(&g_deg[g_dst[e]], 1.0f);
}

__global__ void dinv_kernel() {
    int i = blockIdx.x * 256 + threadIdx.x;
    if (i < NN) g_dinv[i] = rsqrtf(fmaxf(g_deg[i], 1.0f));
}

// ---------------------------------------------------------------------------
// Y[N,64] = relu(X[N,K] @ W[K,64] + B) with packed f32x2 mainloop.
// xs: k-transposed (rows naturally paired). ws2: cols duplicated, XOR-block-
// swizzled so mainloop LDS.128s are conflict-free.
// WRITE_G: also G = Y * dinv (slot gslot) and zero msg (slot 3).
template <int K, bool WRITE_G>
__global__ __launch_bounds__(256)
void gemm_relu_kernel(const float* __restrict__ Xext, int xslot,
                      const float* __restrict__ W, const float* __restrict__ B,
                      int yslot, int gslot) {
    const float* X = Xext ? Xext : slot(xslot);
    float* Y = slot(yslot);

    __shared__ float xs[64 * 68];    // xs[k*68 + r] = X[node r][k]
    __shared__ float ws2[64 * 128];  // dup+swizzled: block blk^(k&31), cols 2x

    int tid = threadIdx.x;
    int tx = tid & 15, ty = tid >> 4;
    int nodeBase = blockIdx.x * 64;

    unsigned long long acc[2][4];  // [rowpair][col]; lo=row 4ty+2rp, hi=+1
#pragma unroll
    for (int i = 0; i < 2; i++)
#pragma unroll
        for (int j = 0; j < 4; j++) acc[i][j] = 0ull;

    for (int kc = 0; kc < K; kc += 64) {
        // stage X transposed
#pragma unroll
        for (int i = 0; i < 4; i++) {
            int p = i * 256 + tid;
            int r = p >> 4;
            int c4 = p & 15;
            int node = nodeBase + r;
            float4 v = make_float4(0.f, 0.f, 0.f, 0.f);
            if (node < NN)
                v = *(const float4*)(X + (size_t)node * K + kc + c4 * 4);
            int k0 = c4 * 4;
            xs[(k0 + 0) * 68 + r] = v.x;
            xs[(k0 + 1) * 68 + r] = v.y;
            xs[(k0 + 2) * 68 + r] = v.z;
            xs[(k0 + 3) * 68 + r] = v.w;
        }
        // stage W duplicated + swizzled
#pragma unroll
        for (int i = 0; i < 4; i++) {
            int p = i * 256 + tid;
            int kk = p >> 4;     // 0..63
            int c4 = p & 15;     // cols 4c4..4c4+3
            float4 w = *(const float4*)(W + (size_t)(kc + kk) * 64 + c4 * 4);
            int kb = kk & 31;
            float4 d0 = make_float4(w.x, w.x, w.y, w.y);
            float4 d1 = make_float4(w.z, w.z, w.w, w.w);
            *(float4*)&ws2[kk * 128 + (((2 * c4)     ^ kb) << 2)] = d0;
            *(float4*)&ws2[kk * 128 + (((2 * c4 + 1) ^ kb) << 2)] = d1;
        }
        __syncthreads();
#pragma unroll
        for (int k = 0; k < 64; k++) {
            ulonglong2 a = *(const ulonglong2*)&xs[k * 68 + ty * 4];
            int kb = k & 31;
            ulonglong2 b0 = *(const ulonglong2*)&ws2[k * 128 + (((2 * tx)     ^ kb) << 2)];
            ulonglong2 b1 = *(const ulonglong2*)&ws2[k * 128 + (((2 * tx + 1) ^ kb) << 2)];
            acc[0][0] = fma2(a.x, b0.x, acc[0][0]);
            acc[1][0] = fma2(a.y, b0.x, acc[1][0]);
            acc[0][1] = fma2(a.x, b0.y, acc[0][1]);
            acc[1][1] = fma2(a.y, b0.y, acc[1][1]);
            acc[0][2] = fma2(a.x, b1.x, acc[0][2]);
            acc[1][2] = fma2(a.y, b1.x, acc[1][2]);
            acc[0][3] = fma2(a.x, b1.y, acc[0][3]);
            acc[1][3] = fma2(a.y, b1.y, acc[1][3]);
        }
        __syncthreads();
    }

    float4 bb = *(const float4*)&B[tx * 4];
#pragma unroll
    for (int i = 0; i < 4; i++) {
        int node = nodeBase + ty * 4 + i;
        if (node < NN) {
            int rp = i >> 1;
            float2 c0 = unpack2(acc[rp][0]);
            float2 c1 = unpack2(acc[rp][1]);
            float2 c2 = unpack2(acc[rp][2]);
            float2 c3 = unpack2(acc[rp][3]);
            float4 o;
            if (i & 1) o = make_float4(c0.y, c1.y, c2.y, c3.y);
            else       o = make_float4(c0.x, c1.x, c2.x, c3.x);
            o.x = fmaxf(o.x + bb.x, 0.0f);
            o.y = fmaxf(o.y + bb.y, 0.0f);
            o.z = fmaxf(o.z + bb.z, 0.0f);
            o.w = fmaxf(o.w + bb.w, 0.0f);
            *(float4*)(Y + (size_t)node * 64 + tx * 4) = o;
            if (WRITE_G) {
                float di = g_dinv[node];
                *(float4*)(slot(gslot) + (size_t)node * 64 + tx * 4) =
                    make_float4(o.x * di, o.y * di, o.z * di, o.w * di);
                *(float4*)(slot(3) + (size_t)node * 64 + tx * 4) =
                    make_float4(0.f, 0.f, 0.f, 0.f);
            }
        }
    }
}

// ---------------------------------------------------------------------------
// msg[dst] += g[src] over all edges. 16 lanes per edge, float4 RED per lane.
__global__ __launch_bounds__(256)
void scatter_kernel(int gslot, int mslot) {
    const float4* g = (const float4*)slot(gslot);
    float4* msg = (float4*)slot(mslot);

    int t = blockIdx.x * 256 + threadIdx.x;
    int e = t >> 4;              // grid sized exactly
    int lane = threadIdx.x & 15;

    int s = g_src[e];
    int d = g_dst[e];

    float4 v = g[(size_t)s * 16 + lane];
#if defined(__CUDA_ARCH__) && (__CUDA_ARCH__ >= 900)
    atomicAdd(&msg[(size_t)d * 16 + lane], v);
#else
    float* mp = (float*)&msg[(size_t)d * 16 + lane];
    atomicAdd(mp + 0, v.x);
    atomicAdd(mp + 1, v.y);
    atomicAdd(mp + 2, v.z);
    atomicAdd(mp + 3, v.w);
#endif
}

// ---------------------------------------------------------------------------
// f1 = f0 - msg*dinv ; g = f1*dinv ; msg = 0
__global__ __launch_bounds__(256)
void update_kernel(int f0slot, int msgslot, int f1slot, int gslot) {
    int i = blockIdx.x * 256 + threadIdx.x;
    if (i < NN * 16) {
        const float4* f0 = (const float4*)slot(f0slot);
        float4* msg = (float4*)slot(msgslot);
        float4* f1 = (float4*)slot(f1slot);
        float4* g = (float4*)slot(gslot);
        float di = g_dinv[i >> 4];
        float4 a = f0[i], m = msg[i];
        float4 f;
        f.x = a.x - m.x * di;
        f.y = a.y - m.y * di;
        f.z = a.z - m.z * di;
        f.w = a.w - m.w * di;
        f1[i] = f;
        g[i] = make_float4(f.x * di, f.y * di, f.z * di, f.w * di);
        msg[i] = make_float4(0.f, 0.f, 0.f, 0.f);
    }
}

// ---------------------------------------------------------------------------
// Final: f2 = f1 - msg*dinv (on the fly); hf = relu(sum_j f_j @ A_j + bm1);
// out = hf @ Wm2 + bm2. f32x2 mainloop like the GEMMs.
__global__ __launch_bounds__(256)
void final_kernel(int f0slot, int f1slot, int msgslot,
                  const float* __restrict__ Wm1, const float* __restrict__ bm1,
                  const float* __restrict__ Wm2, const float* __restrict__ bm2,
                  float* __restrict__ out) {
    const float4* f0 = (const float4*)slot(f0slot);
    const float4* f1 = (const float4*)slot(f1slot);
    const float4* msg = (const float4*)slot(msgslot);

    __shared__ float fs[64 * 68];    // transposed f tile; reused for hf
    __shared__ float as2[64 * 128];  // A_j dup+swizzled
    __shared__ float wm2s[128];

    int tid = threadIdx.x;
    int tx = tid & 15, ty = tid >> 4;
    int nodeBase = blockIdx.x * 64;

    if (tid < 128) wm2s[tid] = Wm2[tid];

    unsigned long long acc[2][4];
#pragma unroll
    for (int i = 0; i < 2; i++)
#pragma unroll
        for (int j = 0; j < 4; j++) acc[i][j] = 0ull;

    const float4* Wm1_4 = (const float4*)Wm1;

    for (int j = 0; j < 3; j++) {
        float c0 = COEF[j][0], c1 = COEF[j][1], c2 = COEF[j][2];
        // build A_j dup+swizzled
#pragma unroll
        for (int i = 0; i < 4; i++) {
            int p = i * 256 + tid;
            int kk = p >> 4;
            int c4 = p & 15;
            float4 w0 = Wm1_4[p];
            float4 w1 = Wm1_4[1024 + p];
            float4 w2 = Wm1_4[2048 + p];
            float4 a;
            a.x = c0 * w0.x + c1 * w1.x + c2 * w2.x;
            a.y = c0 * w0.y + c1 * w1.y + c2 * w2.y;
            a.z = c0 * w0.z + c1 * w1.z + c2 * w2.z;
            a.w = c0 * w0.w + c1 * w1.w + c2 * w2.w;
            int kb = kk & 31;
            *(float4*)&as2[kk * 128 + (((2 * c4)     ^ kb) << 2)] =
                make_float4(a.x, a.x, a.y, a.y);
            *(float4*)&as2[kk * 128 + (((2 * c4 + 1) ^ kb) << 2)] =
                make_float4(a.z, a.z, a.w, a.w);
        }
        // stage f_j transposed
#pragma unroll
        for (int i = 0; i < 4; i++) {
            int p = i * 256 + tid;
            int r = p >> 4, c4 = p & 15;
            int node = nodeBase + r;
            float4 v = make_float4(0.f, 0.f, 0.f, 0.f);
            if (node < NN) {
                int idx = node * 16 + c4;
                if (j == 0) {
                    v = f0[idx];
                } else if (j == 1) {
                    v = f1[idx];
                } else {
                    float4 a1 = f1[idx], m = msg[idx];
                    float di = g_dinv[node];
                    v.x = a1.x - m.x * di;
                    v.y = a1.y - m.y * di;
                    v.z = a1.z - m.z * di;
                    v.w = a1.w - m.w * di;
                }
            }
            int k0 = c4 * 4;
            fs[(k0 + 0) * 68 + r] = v.x;
            fs[(k0 + 1) * 68 + r] = v.y;
            fs[(k0 + 2) * 68 + r] = v.z;
            fs[(k0 + 3) * 68 + r] = v.w;
        }
        __syncthreads();
#pragma unroll
        for (int k = 0; k < 64; k++) {
            ulonglong2 a = *(const ulonglong2*)&fs[k * 68 + ty * 4];
            int kb = k & 31;
            ulonglong2 b0 = *(const ulonglong2*)&as2[k * 128 + (((2 * tx)     ^ kb) << 2)];
            ulonglong2 b1 = *(const ulonglong2*)&as2[k * 128 + (((2 * tx + 1) ^ kb) << 2)];
            acc[0][0] = fma2(a.x, b0.x, acc[0][0]);
            acc[1][0] = fma2(a.y, b0.x, acc[1][0]);
            acc[0][1] = fma2(a.x, b0.y, acc[0][1]);
            acc[1][1] = fma2(a.y, b0.y, acc[1][1]);
            acc[0][2] = fma2(a.x, b1.x, acc[0][2]);
            acc[1][2] = fma2(a.y, b1.x, acc[1][2]);
            acc[0][3] = fma2(a.x, b1.y, acc[0][3]);
            acc[1][3] = fma2(a.y, b1.y, acc[1][3]);
        }
        __syncthreads();
    }

    // bias + relu -> store hf into fs as [node][col], stride 68
    float4 bb = *(const float4*)&bm1[tx * 4];
#pragma unroll
    for (int i = 0; i < 4; i++) {
        int r = ty * 4 + i;
        int rp = i >> 1;
        float2 c0 = unpack2(acc[rp][0]);
        float2 c1 = unpack2(acc[rp][1]);
        float2 c2 = unpack2(acc[rp][2]);
        float2 c3 = unpack2(acc[rp][3]);
        float4 o;
        if (i & 1) o = make_float4(c0.y, c1.y, c2.y, c3.y);
        else       o = make_float4(c0.x, c1.x, c2.x, c3.x);
        o.x = fmaxf(o.x + bb.x, 0.0f);
        o.y = fmaxf(o.y + bb.y, 0.0f);
        o.z = fmaxf(o.z + bb.z, 0.0f);
        o.w = fmaxf(o.w + bb.w, 0.0f);
        *(float4*)&fs[r * 68 + tx * 4] = o;
    }
    __syncthreads();

    // out[n][c] = bm2[c] + sum_k hf[n][k] * Wm2[k][c]
    if (tid < 128) {
        int n = tid >> 1, c = tid & 1;
        int node = nodeBase + n;
        if (node < NN) {
            float s = bm2[c];
#pragma unroll
            for (int k = 0; k < 64; k++) s += fs[n * 68 + k] * wm2s[k * 2 + c];
            out[(size_t)node * 2 + c] = s;
        }
    }
}

// ---------------------------------------------------------------------------
extern "C" void kernel_launch(void* const* d_in, const int* in_sizes, int n_in,
                              void* d_out, int out_size) {
    const float* x = (const float*)d_in[0];
    const void* ei = d_in[1];
    const float* W1 = (const float*)d_in[2];
    const float* b1 = (const float*)d_in[3];
    const float* W2 = (const float*)d_in[4];
    const float* b2 = (const float*)d_in[5];
    const float* Wm1 = (const float*)d_in[6];
    const float* bm1 = (const float*)d_in[7];
    const float* Wm2 = (const float*)d_in[8];
    const float* bm2 = (const float*)d_in[9];
    float* out = (float*)d_out;

    int nbn = (NN + 255) / 256;
    int nbe = (NE + 255) / 256;

    zero_detect_kernel<<<nbn, 256>>>(ei);
    convert_kernel<<<nbe, 256>>>(ei);
    count_kernel<<<nbe, 256>>>();
    dinv_kernel<<<nbn, 256>>>();

    int nb = (NN + 63) / 64;  // 1563
    // h1 = relu(x @ W1 + b1)                       -> slot 0
    gemm_relu_kernel<128, false><<<nb, 256>>>(x, -1, W1, b1, 0, -1);
    // f0 -> slot 1 ; g = f0*dinv -> slot 2 ; msg(slot 3) = 0  (fused prep)
    gemm_relu_kernel<64, true><<<nb, 256>>>(nullptr, 0, W2, b2, 1, 2);

    int nv = (NN * 16 + 255) / 256;
    int ns = (NE * 16) / 256;  // 100000 blocks

    scatter_kernel<<<ns, 256>>>(2, 3);
    update_kernel<<<nv, 256>>>(1, 3, 0, 2);
    scatter_kernel<<<ns, 256>>>(2, 3);

    final_kernel<<<nb, 256>>>(1, 0, 3, Wm1, bm1, Wm2, bm2, out);
}

// round 5
// speedup vs baseline: 1.5331x; 1.5331x over previous
#include <cuda_runtime.h>

#define NN 100000
#define NE 1600000

// Scratch slots, each NN*64 floats (25.6MB): 0..3
__device__ float g_scratch[4ull * NN * 64];
__device__ float g_deg[NN];
__device__ float g_dinv[NN];
__device__ int g_src[NE];
__device__ int g_dst[NE];
__device__ int g_is64;

// A_j = sum_s COEF[s][j] * Wm1_s  (THETAS for D=2 folded)
__constant__ float COEF[3][3] = {
    {3.0f,  0.0f,  0.0f},
    {-3.0f, 3.0f,  0.0f},
    {0.75f, -1.5f, 0.75f}
};

__device__ __forceinline__ float* slot(int s) {
    return g_scratch + (size_t)s * (NN * 64);
}

// ---------------------------------------------------------------------------
// Zero degree counters; thread 0 detects edge_index dtype (int64 data has all
// high halves zero since indices < 1e5).
__global__ void zero_detect_kernel(const void* ei) {
    int i = blockIdx.x * 256 + threadIdx.x;
    if (i < NN) g_deg[i] = 0.0f;
    if (i == 0) {
        const unsigned long long* p = (const unsigned long long*)ei;
        int is64 = 1;
        for (int k = 0; k < 64; k++)
            if ((p[k] >> 32) != 0ull) { is64 = 0; break; }
        g_is64 = is64;
    }
}

// Convert edge_index to int32 src/dst AND count in-degrees in one pass.
__global__ void convert_count_kernel(const void* ei) {
    int e = blockIdx.x * 256 + threadIdx.x;
    if (e < NE) {
        int s, d;
        if (g_is64) {
            const long long* p = (const long long*)ei;
            s = (int)p[e]; d = (int)p[NE + e];
        } else {
            const int* p = (const int*)ei;
            s = p[e]; d = p[NE + e];
        }
        g_src[e] = s;
        g_dst[e] = d;
        atomicAdd(&g_deg[d], 1.0f);
    }
}

__global__ void dinv_kernel() {
    int i = blockIdx.x * 256 + threadIdx.x;
    if (i < NN) g_dinv[i] = rsqrtf(fmaxf(g_deg[i], 1.0f));
}

// ---------------------------------------------------------------------------
// Y[N,64] = relu(X[N,K] @ W[K,64] + B), K in {64,128}
// 64-node x 64-col tile per block, 256 threads, 4x4 register blocking.
// WRITE_G: also write G = Y * dinv (slot gslot) and zero msg (slot 3).
template <int K, bool WRITE_G>
__global__ __launch_bounds__(256)
void gemm_relu_kernel(const float* __restrict__ Xext, int xslot,
                      const float* __restrict__ W, const float* __restrict__ B,
                      int yslot, int gslot) {
    const float* X = Xext ? Xext : slot(xslot);
    float* Y = slot(yslot);

    __shared__ float xs[64 * 68];  // transposed: xs[k][node], stride 68
    __shared__ float ws[64 * 64];  // ws[k][col]

    int tid = threadIdx.x;
    int tx = tid & 15, ty = tid >> 4;
    int nodeBase = blockIdx.x * 64;

    float acc[4][4];
#pragma unroll
    for (int i = 0; i < 4; i++)
#pragma unroll
        for (int j = 0; j < 4; j++) acc[i][j] = 0.0f;

    for (int kc = 0; kc < K; kc += 64) {
#pragma unroll
        for (int i = 0; i < 4; i++) {
            int p = i * 256 + tid;
            int r = p >> 4;
            int c4 = p & 15;
            int node = nodeBase + r;
            float4 v = make_float4(0.f, 0.f, 0.f, 0.f);
            if (node < NN)
                v = *(const float4*)(X + (size_t)node * K + kc + c4 * 4);
            int k0 = c4 * 4;
            xs[(k0 + 0) * 68 + r] = v.x;
            xs[(k0 + 1) * 68 + r] = v.y;
            xs[(k0 + 2) * 68 + r] = v.z;
            xs[(k0 + 3) * 68 + r] = v.w;
        }
#pragma unroll
        for (int i = 0; i < 4; i++) {
            int p = i * 256 + tid;
            ((float4*)ws)[p] =
                *(const float4*)(W + (size_t)(kc + (p >> 4)) * 64 + (p & 15) * 4);
        }
        __syncthreads();
#pragma unroll
        for (int k = 0; k < 64; k++) {
            float4 a = *(float4*)&xs[k * 68 + ty * 4];
            float4 b = *(float4*)&ws[k * 64 + tx * 4];
            acc[0][0] += a.x * b.x; acc[0][1] += a.x * b.y; acc[0][2] += a.x * b.z; acc[0][3] += a.x * b.w;
            acc[1][0] += a.y * b.x; acc[1][1] += a.y * b.y; acc[1][2] += a.y * b.z; acc[1][3] += a.y * b.w;
            acc[2][0] += a.z * b.x; acc[2][1] += a.z * b.y; acc[2][2] += a.z * b.z; acc[2][3] += a.z * b.w;
            acc[3][0] += a.w * b.x; acc[3][1] += a.w * b.y; acc[3][2] += a.w * b.z; acc[3][3] += a.w * b.w;
        }
        __syncthreads();
    }

    float4 bb = *(const float4*)&B[tx * 4];
#pragma unroll
    for (int i = 0; i < 4; i++) {
        int node = nodeBase + ty * 4 + i;
        if (node < NN) {
            float4 o;
            o.x = fmaxf(acc[i][0] + bb.x, 0.0f);
            o.y = fmaxf(acc[i][1] + bb.y, 0.0f);
            o.z = fmaxf(acc[i][2] + bb.z, 0.0f);
            o.w = fmaxf(acc[i][3] + bb.w, 0.0f);
            *(float4*)(Y + (size_t)node * 64 + tx * 4) = o;
            if (WRITE_G) {
                float di = g_dinv[node];
                *(float4*)(slot(gslot) + (size_t)node * 64 + tx * 4) =
                    make_float4(o.x * di, o.y * di, o.z * di, o.w * di);
                *(float4*)(slot(3) + (size_t)node * 64 + tx * 4) =
                    make_float4(0.f, 0.f, 0.f, 0.f);
            }
        }
    }
}

// ---------------------------------------------------------------------------
// msg[dst] += g[src] over all edges. 16 lanes per edge, float4 RED per lane.
__global__ __launch_bounds__(256)
void scatter_kernel(int gslot, int mslot) {
    const float4* g = (const float4*)slot(gslot);
    float4* msg = (float4*)slot(mslot);

    int t = blockIdx.x * 256 + threadIdx.x;
    int e = t >> 4;              // grid sized exactly: e < NE always
    int lane = threadIdx.x & 15;

    int s = g_src[e];
    int d = g_dst[e];

    float4 v = g[(size_t)s * 16 + lane];
#if defined(__CUDA_ARCH__) && (__CUDA_ARCH__ >= 900)
    atomicAdd(&msg[(size_t)d * 16 + lane], v);
#else
    float* mp = (float*)&msg[(size_t)d * 16 + lane];
    atomicAdd(mp + 0, v.x);
    atomicAdd(mp + 1, v.y);
    atomicAdd(mp + 2, v.z);
    atomicAdd(mp + 3, v.w);
#endif
}

// ---------------------------------------------------------------------------
// f1 = f0 - msg*dinv ; g = f1*dinv ; msg = 0
__global__ __launch_bounds__(256)
void update_kernel(int f0slot, int msgslot, int f1slot, int gslot) {
    int i = blockIdx.x * 256 + threadIdx.x;
    if (i < NN * 16) {
        const float4* f0 = (const float4*)slot(f0slot);
        float4* msg = (float4*)slot(msgslot);
        float4* f1 = (float4*)slot(f1slot);
        float4* g = (float4*)slot(gslot);
        float di = g_dinv[i >> 4];
        float4 a = f0[i], m = msg[i];
        float4 f;
        f.x = a.x - m.x * di;
        f.y = a.y - m.y * di;
        f.z = a.z - m.z * di;
        f.w = a.w - m.w * di;
        f1[i] = f;
        g[i] = make_float4(f.x * di, f.y * di, f.z * di, f.w * di);
        msg[i] = make_float4(0.f, 0.f, 0.f, 0.f);
    }
}

// ---------------------------------------------------------------------------
// Final: f2 = f1 - msg*dinv (on the fly); hf = relu(sum_j f_j @ A_j + bm1);
// out = hf @ Wm2 + bm2.
__global__ __launch_bounds__(256)
void final_kernel(int f0slot, int f1slot, int msgslot,
                  const float* __restrict__ Wm1, const float* __restrict__ bm1,
                  const float* __restrict__ Wm2, const float* __restrict__ bm2,
                  float* __restrict__ out) {
    const float4* f0 = (const float4*)slot(f0slot);
    const float4* f1 = (const float4*)slot(f1slot);
    const float4* msg = (const float4*)slot(msgslot);

    __shared__ float fs[64 * 68];  // transposed f tile, later reused as hf
    __shared__ float as[64 * 64];  // A_j[k][col]
    __shared__ float wm2s[128];

    int tid = threadIdx.x;
    int tx = tid & 15, ty = tid >> 4;
    int nodeBase = blockIdx.x * 64;

    if (tid < 128) wm2s[tid] = Wm2[tid];

    float acc[4][4];
#pragma unroll
    for (int i = 0; i < 4; i++)
#pragma unroll
        for (int j = 0; j < 4; j++) acc[i][j] = 0.0f;

    const float4* Wm1_4 = (const float4*)Wm1;

    for (int j = 0; j < 3; j++) {
        float c0 = COEF[j][0], c1 = COEF[j][1], c2 = COEF[j][2];
        // build A_j (64x64) in smem
#pragma unroll
        for (int i = 0; i < 4; i++) {
            int p = i * 256 + tid;  // p = k*16 + c4
            float4 w0 = Wm1_4[p];
            float4 w1 = Wm1_4[1024 + p];
            float4 w2 = Wm1_4[2048 + p];
            float4 a;
            a.x = c0 * w0.x + c1 * w1.x + c2 * w2.x;
            a.y = c0 * w0.y + c1 * w1.y + c2 * w2.y;
            a.z = c0 * w0.z + c1 * w1.z + c2 * w2.z;
            a.w = c0 * w0.w + c1 * w1.w + c2 * w2.w;
            ((float4*)as)[p] = a;
        }
        // load f_j tile transposed into fs
#pragma unroll
        for (int i = 0; i < 4; i++) {
            int p = i * 256 + tid;
            int r = p >> 4, c4 = p & 15;
            int node = nodeBase + r;
            float4 v = make_float4(0.f, 0.f, 0.f, 0.f);
            if (node < NN) {
                int idx = node * 16 + c4;
                if (j == 0) {
                    v = f0[idx];
                } else if (j == 1) {
                    v = f1[idx];
                } else {
                    float4 a1 = f1[idx], m = msg[idx];
                    float di = g_dinv[node];
                    v.x = a1.x - m.x * di;
                    v.y = a1.y - m.y * di;
                    v.z = a1.z - m.z * di;
                    v.w = a1.w - m.w * di;
                }
            }
            int k0 = c4 * 4;
            fs[(k0 + 0) * 68 + r] = v.x;
            fs[(k0 + 1) * 68 + r] = v.y;
            fs[(k0 + 2) * 68 + r] = v.z;
            fs[(k0 + 3) * 68 + r] = v.w;
        }
        __syncthreads();
#pragma unroll
        for (int k = 0; k < 64; k++) {
            float4 a = *(float4*)&fs[k * 68 + ty * 4];
            float4 b = *(float4*)&as[k * 64 + tx * 4];
            acc[0][0] += a.x * b.x; acc[0][1] += a.x * b.y; acc[0][2] += a.x * b.z; acc[0][3] += a.x * b.w;
            acc[1][0] += a.y * b.x; acc[1][1] += a.y * b.y; acc[1][2] += a.y * b.z; acc[1][3] += a.y * b.w;
            acc[2][0] += a.z * b.x; acc[2][1] += a.z * b.y; acc[2][2] += a.z * b.z; acc[2][3] += a.z * b.w;
            acc[3][0] += a.w * b.x; acc[3][1] += a.w * b.y; acc[3][2] += a.w * b.z; acc[3][3] += a.w * b.w;
        }
        __syncthreads();
    }

    // bias + relu -> store hf into fs as [node][col], stride 68
    float4 bb = *(const float4*)&bm1[tx * 4];
#pragma unroll
    for (int i = 0; i < 4; i++) {
        int r = ty * 4 + i;
        float4 o;
        o.x = fmaxf(acc[i][0] + bb.x, 0.0f);
        o.y = fmaxf(acc[i][1] + bb.y, 0.0f);
        o.z = fmaxf(acc[i][2] + bb.z, 0.0f);
        o.w = fmaxf(acc[i][3] + bb.w, 0.0f);
        *(float4*)&fs[r * 68 + tx * 4] = o;
    }
    __syncthreads();

    // out[n][c] = bm2[c] + sum_k hf[n][k] * Wm2[k][c]
    if (tid < 128) {
        int n = tid >> 1, c = tid & 1;
        int node = nodeBase + n;
        if (node < NN) {
            float s = bm2[c];
#pragma unroll
            for (int k = 0; k < 64; k++) s += fs[n * 68 + k] * wm2s[k * 2 + c];
            out[(size_t)node * 2 + c] = s;
        }
    }
}

// ---------------------------------------------------------------------------
extern "C" void kernel_launch(void* const* d_in, const int* in_sizes, int n_in,
                              void* d_out, int out_size) {
    const float* x = (const float*)d_in[0];
    const void* ei = d_in[1];
    const float* W1 = (const float*)d_in[2];
    const float* b1 = (const float*)d_in[3];
    const float* W2 = (const float*)d_in[4];
    const float* b2 = (const float*)d_in[5];
    const float* Wm1 = (const float*)d_in[6];
    const float* bm1 = (const float*)d_in[7];
    const float* Wm2 = (const float*)d_in[8];
    const float* bm2 = (const float*)d_in[9];
    float* out = (float*)d_out;

    int nbn = (NN + 255) / 256;
    int nbe = (NE + 255) / 256;

    zero_detect_kernel<<<nbn, 256>>>(ei);       // launch 1
    convert_count_kernel<<<nbe, 256>>>(ei);     // launch 2
    dinv_kernel<<<nbn, 256>>>();                // launch 3

    int nb = (NN + 63) / 64;  // 1563
    // h1 = relu(x @ W1 + b1)                       -> slot 0      launch 4
    gemm_relu_kernel<128, false><<<nb, 256>>>(x, -1, W1, b1, 0, -1);
    // f0 -> slot 1 ; g = f0*dinv -> slot 2 ; msg(slot3) = 0       launch 5
    gemm_relu_kernel<64, true><<<nb, 256>>>(nullptr, 0, W2, b2, 1, 2);

    int nv = (NN * 16 + 255) / 256;
    int ns = (NE * 16) / 256;  // 100000 blocks

    scatter_kernel<<<ns, 256>>>(2, 3);          // launch 6 (profiled)
    update_kernel<<<nv, 256>>>(1, 3, 0, 2);     // launch 7
    scatter_kernel<<<ns, 256>>>(2, 3);          // launch 8

    final_kernel<<<nb, 256>>>(1, 0, 3, Wm1, bm1, Wm2, bm2, out);  // launch 9
}

// round 6
// speedup vs baseline: 1.7078x; 1.1139x over previous
#include <cuda_runtime.h>

#define NN 100000
#define NE 1600000

// Scratch slots, each NN*64 floats (25.6MB): 0..3
__device__ float g_scratch[4ull * NN * 64];
__device__ float g_deg[NN];
__device__ float g_dinv[NN];
__device__ int g_src[NE];
__device__ int g_dst[NE];
__device__ int g_is64;

// A_j = sum_s COEF[s][j] * Wm1_s  (THETAS for D=2 folded)
__constant__ float COEF[3][3] = {
    {3.0f,  0.0f,  0.0f},
    {-3.0f, 3.0f,  0.0f},
    {0.75f, -1.5f, 0.75f}
};

__device__ __forceinline__ float* slot(int s) {
    return g_scratch + (size_t)s * (NN * 64);
}

// ---------------------------------------------------------------------------
// Zero degree counters; thread 0 detects edge_index dtype (int64 data has all
// high halves zero since indices < 1e5).
__global__ void zero_detect_kernel(const void* ei) {
    int i = blockIdx.x * 256 + threadIdx.x;
    if (i < NN) g_deg[i] = 0.0f;
    if (i == 0) {
        const unsigned long long* p = (const unsigned long long*)ei;
        int is64 = 1;
        for (int k = 0; k < 64; k++)
            if ((p[k] >> 32) != 0ull) { is64 = 0; break; }
        g_is64 = is64;
    }
}

// Convert edge_index to int32 src/dst AND count in-degrees in one pass.
__global__ void convert_count_kernel(const void* ei) {
    int e = blockIdx.x * 256 + threadIdx.x;
    if (e < NE) {
        int s, d;
        if (g_is64) {
            const long long* p = (const long long*)ei;
            s = (int)p[e]; d = (int)p[NE + e];
        } else {
            const int* p = (const int*)ei;
            s = p[e]; d = p[NE + e];
        }
        g_src[e] = s;
        g_dst[e] = d;
        atomicAdd(&g_deg[d], 1.0f);
    }
}

__global__ void dinv_kernel() {
    int i = blockIdx.x * 256 + threadIdx.x;
    if (i < NN) g_dinv[i] = rsqrtf(fmaxf(g_deg[i], 1.0f));
}

// ---------------------------------------------------------------------------
// Shared mainloop macro piece: 4 rows (float4 over k) x 4 cols, k grouped by 4.
// xs: [row][k] natural layout, stride 68 floats (16B aligned, conflict-free
// float4 staging). ws: [k][col].
__device__ __forceinline__ void mma_chunk64(
    const float* xs, const float* ws, int tx, int ty, float acc[4][4]) {
#pragma unroll
    for (int k4 = 0; k4 < 16; k4++) {
        float4 a0 = *(const float4*)&xs[(ty * 4 + 0) * 68 + k4 * 4];
        float4 a1 = *(const float4*)&xs[(ty * 4 + 1) * 68 + k4 * 4];
        float4 a2 = *(const float4*)&xs[(ty * 4 + 2) * 68 + k4 * 4];
        float4 a3 = *(const float4*)&xs[(ty * 4 + 3) * 68 + k4 * 4];
        float r0[4] = {a0.x, a0.y, a0.z, a0.w};
        float r1[4] = {a1.x, a1.y, a1.z, a1.w};
        float r2[4] = {a2.x, a2.y, a2.z, a2.w};
        float r3[4] = {a3.x, a3.y, a3.z, a3.w};
#pragma unroll
        for (int j = 0; j < 4; j++) {
            float4 b = *(const float4*)&ws[(k4 * 4 + j) * 64 + tx * 4];
            acc[0][0] += r0[j] * b.x; acc[0][1] += r0[j] * b.y;
            acc[0][2] += r0[j] * b.z; acc[0][3] += r0[j] * b.w;
            acc[1][0] += r1[j] * b.x; acc[1][1] += r1[j] * b.y;
            acc[1][2] += r1[j] * b.z; acc[1][3] += r1[j] * b.w;
            acc[2][0] += r2[j] * b.x; acc[2][1] += r2[j] * b.y;
            acc[2][2] += r2[j] * b.z; acc[2][3] += r2[j] * b.w;
            acc[3][0] += r3[j] * b.x; acc[3][1] += r3[j] * b.y;
            acc[3][2] += r3[j] * b.z; acc[3][3] += r3[j] * b.w;
        }
    }
}

// ---------------------------------------------------------------------------
// Y[N,64] = relu(X[N,K] @ W[K,64] + B), K in {64,128}
// 64-node x 64-col tile per block, 256 threads, 4x4 register blocking.
// WRITE_G: also write G = Y * dinv (slot gslot) and zero msg (slot 3).
template <int K, bool WRITE_G>
__global__ __launch_bounds__(256)
void gemm_relu_kernel(const float* __restrict__ Xext, int xslot,
                      const float* __restrict__ W, const float* __restrict__ B,
                      int yslot, int gslot) {
    const float* X = Xext ? Xext : slot(xslot);
    float* Y = slot(yslot);

    __shared__ float xs[64 * 68];  // natural: xs[row][k], stride 68
    __shared__ float ws[64 * 64];  // ws[k][col]

    int tid = threadIdx.x;
    int tx = tid & 15, ty = tid >> 4;
    int nodeBase = blockIdx.x * 64;

    float acc[4][4];
#pragma unroll
    for (int i = 0; i < 4; i++)
#pragma unroll
        for (int j = 0; j < 4; j++) acc[i][j] = 0.0f;

    for (int kc = 0; kc < K; kc += 64) {
        // stage X natural [row][k] — contiguous float4 stores, conflict-free
#pragma unroll
        for (int i = 0; i < 4; i++) {
            int p = i * 256 + tid;
            int r = p >> 4;
            int c4 = p & 15;
            int node = nodeBase + r;
            float4 v = make_float4(0.f, 0.f, 0.f, 0.f);
            if (node < NN)
                v = *(const float4*)(X + (size_t)node * K + kc + c4 * 4);
            *(float4*)&xs[r * 68 + c4 * 4] = v;
        }
#pragma unroll
        for (int i = 0; i < 4; i++) {
            int p = i * 256 + tid;
            ((float4*)ws)[p] =
                *(const float4*)(W + (size_t)(kc + (p >> 4)) * 64 + (p & 15) * 4);
        }
        __syncthreads();
        mma_chunk64(xs, ws, tx, ty, acc);
        __syncthreads();
    }

    float4 bb = *(const float4*)&B[tx * 4];
#pragma unroll
    for (int i = 0; i < 4; i++) {
        int node = nodeBase + ty * 4 + i;
        if (node < NN) {
            float4 o;
            o.x = fmaxf(acc[i][0] + bb.x, 0.0f);
            o.y = fmaxf(acc[i][1] + bb.y, 0.0f);
            o.z = fmaxf(acc[i][2] + bb.z, 0.0f);
            o.w = fmaxf(acc[i][3] + bb.w, 0.0f);
            *(float4*)(Y + (size_t)node * 64 + tx * 4) = o;
            if (WRITE_G) {
                float di = g_dinv[node];
                *(float4*)(slot(gslot) + (size_t)node * 64 + tx * 4) =
                    make_float4(o.x * di, o.y * di, o.z * di, o.w * di);
                *(float4*)(slot(3) + (size_t)node * 64 + tx * 4) =
                    make_float4(0.f, 0.f, 0.f, 0.f);
            }
        }
    }
}

// ---------------------------------------------------------------------------
// msg[dst] += g[src] over all edges. 16 lanes per edge, float4 RED per lane.
__global__ __launch_bounds__(256)
void scatter_kernel(int gslot, int mslot) {
    const float4* g = (const float4*)slot(gslot);
    float4* msg = (float4*)slot(mslot);

    int t = blockIdx.x * 256 + threadIdx.x;
    int e = t >> 4;              // grid sized exactly: e < NE always
    int lane = threadIdx.x & 15;

    int s = g_src[e];
    int d = g_dst[e];

    float4 v = g[(size_t)s * 16 + lane];
#if defined(__CUDA_ARCH__) && (__CUDA_ARCH__ >= 900)
    atomicAdd(&msg[(size_t)d * 16 + lane], v);
#else
    float* mp = (float*)&msg[(size_t)d * 16 + lane];
    atomicAdd(mp + 0, v.x);
    atomicAdd(mp + 1, v.y);
    atomicAdd(mp + 2, v.z);
    atomicAdd(mp + 3, v.w);
#endif
}

// ---------------------------------------------------------------------------
// f1 = f0 - msg*dinv ; g = f1*dinv ; msg = 0
__global__ __launch_bounds__(256)
void update_kernel(int f0slot, int msgslot, int f1slot, int gslot) {
    int i = blockIdx.x * 256 + threadIdx.x;
    if (i < NN * 16) {
        const float4* f0 = (const float4*)slot(f0slot);
        float4* msg = (float4*)slot(msgslot);
        float4* f1 = (float4*)slot(f1slot);
        float4* g = (float4*)slot(gslot);
        float di = g_dinv[i >> 4];
        float4 a = f0[i], m = msg[i];
        float4 f;
        f.x = a.x - m.x * di;
        f.y = a.y - m.y * di;
        f.z = a.z - m.z * di;
        f.w = a.w - m.w * di;
        f1[i] = f;
        g[i] = make_float4(f.x * di, f.y * di, f.z * di, f.w * di);
        msg[i] = make_float4(0.f, 0.f, 0.f, 0.f);
    }
}

// ---------------------------------------------------------------------------
// Final: f2 = f1 - msg*dinv (on the fly); hf = relu(sum_j f_j @ A_j + bm1);
// out = hf @ Wm2 + bm2.
__global__ __launch_bounds__(256)
void final_kernel(int f0slot, int f1slot, int msgslot,
                  const float* __restrict__ Wm1, const float* __restrict__ bm1,
                  const float* __restrict__ Wm2, const float* __restrict__ bm2,
                  float* __restrict__ out) {
    const float4* f0 = (const float4*)slot(f0slot);
    const float4* f1 = (const float4*)slot(f1slot);
    const float4* msg = (const float4*)slot(msgslot);

    __shared__ float fs[64 * 68];  // natural [node][k]; reused as hf[node][col]
    __shared__ float as[64 * 64];  // A_j[k][col]
    __shared__ float wm2s[128];

    int tid = threadIdx.x;
    int tx = tid & 15, ty = tid >> 4;
    int nodeBase = blockIdx.x * 64;

    if (tid < 128) wm2s[tid] = Wm2[tid];

    float acc[4][4];
#pragma unroll
    for (int i = 0; i < 4; i++)
#pragma unroll
        for (int j = 0; j < 4; j++) acc[i][j] = 0.0f;

    const float4* Wm1_4 = (const float4*)Wm1;

    for (int j = 0; j < 3; j++) {
        float c0 = COEF[j][0], c1 = COEF[j][1], c2 = COEF[j][2];
        // build A_j (64x64) in smem
#pragma unroll
        for (int i = 0; i < 4; i++) {
            int p = i * 256 + tid;  // p = k*16 + c4
            float4 w0 = Wm1_4[p];
            float4 w1 = Wm1_4[1024 + p];
            float4 w2 = Wm1_4[2048 + p];
            float4 a;
            a.x = c0 * w0.x + c1 * w1.x + c2 * w2.x;
            a.y = c0 * w0.y + c1 * w1.y + c2 * w2.y;
            a.z = c0 * w0.z + c1 * w1.z + c2 * w2.z;
            a.w = c0 * w0.w + c1 * w1.w + c2 * w2.w;
            ((float4*)as)[p] = a;
        }
        // stage f_j natural [node][k]
#pragma unroll
        for (int i = 0; i < 4; i++) {
            int p = i * 256 + tid;
            int r = p >> 4, c4 = p & 15;
            int node = nodeBase + r;
            float4 v = make_float4(0.f, 0.f, 0.f, 0.f);
            if (node < NN) {
                int idx = node * 16 + c4;
                if (j == 0) {
                    v = f0[idx];
                } else if (j == 1) {
                    v = f1[idx];
                } else {
                    float4 a1 = f1[idx], m = msg[idx];
                    float di = g_dinv[node];
                    v.x = a1.x - m.x * di;
                    v.y = a1.y - m.y * di;
                    v.z = a1.z - m.z * di;
                    v.w = a1.w - m.w * di;
                }
            }
            *(float4*)&fs[r * 68 + c4 * 4] = v;
        }
        __syncthreads();
        mma_chunk64(fs, as, tx, ty, acc);
        __syncthreads();
    }

    // bias + relu -> store hf into fs as [node][col], stride 68
    float4 bb = *(const float4*)&bm1[tx * 4];
#pragma unroll
    for (int i = 0; i < 4; i++) {
        int r = ty * 4 + i;
        float4 o;
        o.x = fmaxf(acc[i][0] + bb.x, 0.0f);
        o.y = fmaxf(acc[i][1] + bb.y, 0.0f);
        o.z = fmaxf(acc[i][2] + bb.z, 0.0f);
        o.w = fmaxf(acc[i][3] + bb.w, 0.0f);
        *(float4*)&fs[r * 68 + tx * 4] = o;
    }
    __syncthreads();

    // out[n][c] = bm2[c] + sum_k hf[n][k] * Wm2[k][c]
    if (tid < 128) {
        int n = tid >> 1, c = tid & 1;
        int node = nodeBase + n;
        if (node < NN) {
            float s = bm2[c];
#pragma unroll
            for (int k = 0; k < 64; k++) s += fs[n * 68 + k] * wm2s[k * 2 + c];
            out[(size_t)node * 2 + c] = s;
        }
    }
}

// ---------------------------------------------------------------------------
extern "C" void kernel_launch(void* const* d_in, const int* in_sizes, int n_in,
                              void* d_out, int out_size) {
    const float* x = (const float*)d_in[0];
    const void* ei = d_in[1];
    const float* W1 = (const float*)d_in[2];
    const float* b1 = (const float*)d_in[3];
    const float* W2 = (const float*)d_in[4];
    const float* b2 = (const float*)d_in[5];
    const float* Wm1 = (const float*)d_in[6];
    const float* bm1 = (const float*)d_in[7];
    const float* Wm2 = (const float*)d_in[8];
    const float* bm2 = (const float*)d_in[9];
    float* out = (float*)d_out;

    int nbn = (NN + 255) / 256;
    int nbe = (NE + 255) / 256;

    zero_detect_kernel<<<nbn, 256>>>(ei);
    convert_count_kernel<<<nbe, 256>>>(ei);
    dinv_kernel<<<nbn, 256>>>();

    int nb = (NN + 63) / 64;  // 1563
    // h1 = relu(x @ W1 + b1)                       -> slot 0
    gemm_relu_kernel<128, false><<<nb, 256>>>(x, -1, W1, b1, 0, -1);
    // f0 -> slot 1 ; g = f0*dinv -> slot 2 ; msg(slot3) = 0
    gemm_relu_kernel<64, true><<<nb, 256>>>(nullptr, 0, W2, b2, 1, 2);

    int nv = (NN * 16 + 255) / 256;
    int ns = (NE * 16) / 256;  // 100000 blocks

    scatter_kernel<<<ns, 256>>>(2, 3);
    update_kernel<<<nv, 256>>>(1, 3, 0, 2);
    scatter_kernel<<<ns, 256>>>(2, 3);

    final_kernel<<<nb, 256>>>(1, 0, 3, Wm1, bm1, Wm2, bm2, out);
}

// round 7
// speedup vs baseline: 1.7164x; 1.0051x over previous
#include <cuda_runtime.h>

#define NN 100000
#define NE 1600000

// Scratch slots, each NN*64 floats (25.6MB): 0..3
__device__ float g_scratch[4ull * NN * 64];
__device__ int g_deg[NN];   // zero-init; reset by final_kernel each launch
__device__ int g_src[NE];
__device__ int g_dst[NE];

// A_j = sum_s COEF[s][j] * Wm1_s  (THETAS for D=2 folded)
__constant__ float COEF[3][3] = {
    {3.0f,  0.0f,  0.0f},
    {-3.0f, 3.0f,  0.0f},
    {0.75f, -1.5f, 0.75f}
};

__device__ __forceinline__ float* slot(int s) {
    return g_scratch + (size_t)s * (NN * 64);
}

__device__ __forceinline__ float dinv_of(int node) {
    int d = g_deg[node];
    return rsqrtf((float)(d > 0 ? d : 1));
}

// ---------------------------------------------------------------------------
// Convert edge_index to int32 src/dst AND count in-degrees, one pass.
// Per-block dtype detect: int64 data has all high halves zero (indices < 1e5).
__global__ void convert_count_kernel(const void* ei) {
    __shared__ int s_is64;
    if (threadIdx.x == 0) {
        const unsigned long long* p = (const unsigned long long*)ei;
        int is64 = 1;
        for (int k = 0; k < 64; k++)
            if ((p[k] >> 32) != 0ull) { is64 = 0; break; }
        s_is64 = is64;
    }
    __syncthreads();
    int e = blockIdx.x * 256 + threadIdx.x;
    if (e < NE) {
        int s, d;
        if (s_is64) {
            const long long* p = (const long long*)ei;
            s = (int)p[e]; d = (int)p[NE + e];
        } else {
            const int* p = (const int*)ei;
            s = p[e]; d = p[NE + e];
        }
        g_src[e] = s;
        g_dst[e] = d;
        atomicAdd(&g_deg[d], 1);
    }
}

// ---------------------------------------------------------------------------
// Mainloop: 4 rows (float4 over k) x 4 cols, k grouped by 4.
// xs: [row][k] natural layout, stride 68 (conflict-free float4 staging).
__device__ __forceinline__ void mma_chunk64(
    const float* xs, const float* ws, int tx, int ty, float acc[4][4]) {
#pragma unroll
    for (int k4 = 0; k4 < 16; k4++) {
        float4 a0 = *(const float4*)&xs[(ty * 4 + 0) * 68 + k4 * 4];
        float4 a1 = *(const float4*)&xs[(ty * 4 + 1) * 68 + k4 * 4];
        float4 a2 = *(const float4*)&xs[(ty * 4 + 2) * 68 + k4 * 4];
        float4 a3 = *(const float4*)&xs[(ty * 4 + 3) * 68 + k4 * 4];
        float r0[4] = {a0.x, a0.y, a0.z, a0.w};
        float r1[4] = {a1.x, a1.y, a1.z, a1.w};
        float r2[4] = {a2.x, a2.y, a2.z, a2.w};
        float r3[4] = {a3.x, a3.y, a3.z, a3.w};
#pragma unroll
        for (int j = 0; j < 4; j++) {
            float4 b = *(const float4*)&ws[(k4 * 4 + j) * 64 + tx * 4];
            acc[0][0] += r0[j] * b.x; acc[0][1] += r0[j] * b.y;
            acc[0][2] += r0[j] * b.z; acc[0][3] += r0[j] * b.w;
            acc[1][0] += r1[j] * b.x; acc[1][1] += r1[j] * b.y;
            acc[1][2] += r1[j] * b.z; acc[1][3] += r1[j] * b.w;
            acc[2][0] += r2[j] * b.x; acc[2][1] += r2[j] * b.y;
            acc[2][2] += r2[j] * b.z; acc[2][3] += r2[j] * b.w;
            acc[3][0] += r3[j] * b.x; acc[3][1] += r3[j] * b.y;
            acc[3][2] += r3[j] * b.z; acc[3][3] += r3[j] * b.w;
        }
    }
}

// ---------------------------------------------------------------------------
// Y[N,64] = relu(X[N,K] @ W[K,64] + B), K in {64,128}
// WRITE_G: also write G = Y * dinv (slot gslot) and zero msg (slot 3).
template <int K, bool WRITE_G>
__global__ __launch_bounds__(256)
void gemm_relu_kernel(const float* __restrict__ Xext, int xslot,
                      const float* __restrict__ W, const float* __restrict__ B,
                      int yslot, int gslot) {
    const float* X = Xext ? Xext : slot(xslot);
    float* Y = slot(yslot);

    __shared__ float xs[64 * 68];  // natural: xs[row][k], stride 68
    __shared__ float ws[64 * 64];  // ws[k][col]

    int tid = threadIdx.x;
    int tx = tid & 15, ty = tid >> 4;
    int nodeBase = blockIdx.x * 64;

    float acc[4][4];
#pragma unroll
    for (int i = 0; i < 4; i++)
#pragma unroll
        for (int j = 0; j < 4; j++) acc[i][j] = 0.0f;

    for (int kc = 0; kc < K; kc += 64) {
#pragma unroll
        for (int i = 0; i < 4; i++) {
            int p = i * 256 + tid;
            int r = p >> 4;
            int c4 = p & 15;
            int node = nodeBase + r;
            float4 v = make_float4(0.f, 0.f, 0.f, 0.f);
            if (node < NN)
                v = *(const float4*)(X + (size_t)node * K + kc + c4 * 4);
            *(float4*)&xs[r * 68 + c4 * 4] = v;
        }
#pragma unroll
        for (int i = 0; i < 4; i++) {
            int p = i * 256 + tid;
            ((float4*)ws)[p] =
                *(const float4*)(W + (size_t)(kc + (p >> 4)) * 64 + (p & 15) * 4);
        }
        __syncthreads();
        mma_chunk64(xs, ws, tx, ty, acc);
        __syncthreads();
    }

    float4 bb = *(const float4*)&B[tx * 4];
#pragma unroll
    for (int i = 0; i < 4; i++) {
        int node = nodeBase + ty * 4 + i;
        if (node < NN) {
            float4 o;
            o.x = fmaxf(acc[i][0] + bb.x, 0.0f);
            o.y = fmaxf(acc[i][1] + bb.y, 0.0f);
            o.z = fmaxf(acc[i][2] + bb.z, 0.0f);
            o.w = fmaxf(acc[i][3] + bb.w, 0.0f);
            *(float4*)(Y + (size_t)node * 64 + tx * 4) = o;
            if (WRITE_G) {
                float di = dinv_of(node);
                *(float4*)(slot(gslot) + (size_t)node * 64 + tx * 4) =
                    make_float4(o.x * di, o.y * di, o.z * di, o.w * di);
                *(float4*)(slot(3) + (size_t)node * 64 + tx * 4) =
                    make_float4(0.f, 0.f, 0.f, 0.f);
            }
        }
    }
}

// ---------------------------------------------------------------------------
// msg[dst] += g[src] over all edges. 16 lanes per edge, float4 RED per lane.
__global__ __launch_bounds__(256)
void scatter_kernel(int gslot, int mslot) {
    const float4* g = (const float4*)slot(gslot);
    float4* msg = (float4*)slot(mslot);

    int t = blockIdx.x * 256 + threadIdx.x;
    int e = t >> 4;              // grid sized exactly: e < NE always
    int lane = threadIdx.x & 15;

    int s = g_src[e];
    int d = g_dst[e];

    float4 v = g[(size_t)s * 16 + lane];
#if defined(__CUDA_ARCH__) && (__CUDA_ARCH__ >= 900)
    atomicAdd(&msg[(size_t)d * 16 + lane], v);
#else
    float* mp = (float*)&msg[(size_t)d * 16 + lane];
    atomicAdd(mp + 0, v.x);
    atomicAdd(mp + 1, v.y);
    atomicAdd(mp + 2, v.z);
    atomicAdd(mp + 3, v.w);
#endif
}

// ---------------------------------------------------------------------------
// f1 = f0 - msg*dinv ; g = f1*dinv ; msg = 0
__global__ __launch_bounds__(256)
void update_kernel(int f0slot, int msgslot, int f1slot, int gslot) {
    int i = blockIdx.x * 256 + threadIdx.x;
    if (i < NN * 16) {
        const float4* f0 = (const float4*)slot(f0slot);
        float4* msg = (float4*)slot(msgslot);
        float4* f1 = (float4*)slot(f1slot);
        float4* g = (float4*)slot(gslot);
        float di = dinv_of(i >> 4);
        float4 a = f0[i], m = msg[i];
        float4 f;
        f.x = a.x - m.x * di;
        f.y = a.y - m.y * di;
        f.z = a.z - m.z * di;
        f.w = a.w - m.w * di;
        f1[i] = f;
        g[i] = make_float4(f.x * di, f.y * di, f.z * di, f.w * di);
        msg[i] = make_float4(0.f, 0.f, 0.f, 0.f);
    }
}

// ---------------------------------------------------------------------------
// Final: f2 = f1 - msg*dinv (on the fly); hf = relu(sum_j f_j @ A_j + bm1);
// out = hf @ Wm2 + bm2. Also resets g_deg to 0 for the next graph replay.
__global__ __launch_bounds__(256)
void final_kernel(int f0slot, int f1slot, int msgslot,
                  const float* __restrict__ Wm1, const float* __restrict__ bm1,
                  const float* __restrict__ Wm2, const float* __restrict__ bm2,
                  float* __restrict__ out) {
    const float4* f0 = (const float4*)slot(f0slot);
    const float4* f1 = (const float4*)slot(f1slot);
    const float4* msg = (const float4*)slot(msgslot);

    __shared__ float fs[64 * 68];  // natural [node][k]; reused as hf[node][col]
    __shared__ float as[64 * 64];  // A_j[k][col]
    __shared__ float wm2s[128];

    int tid = threadIdx.x;
    int tx = tid & 15, ty = tid >> 4;
    int nodeBase = blockIdx.x * 64;

    if (tid < 128) wm2s[tid] = Wm2[tid];

    float acc[4][4];
#pragma unroll
    for (int i = 0; i < 4; i++)
#pragma unroll
        for (int j = 0; j < 4; j++) acc[i][j] = 0.0f;

    const float4* Wm1_4 = (const float4*)Wm1;

    for (int j = 0; j < 3; j++) {
        float c0 = COEF[j][0], c1 = COEF[j][1], c2 = COEF[j][2];
        // build A_j (64x64) in smem
#pragma unroll
        for (int i = 0; i < 4; i++) {
            int p = i * 256 + tid;  // p = k*16 + c4
            float4 w0 = Wm1_4[p];
            float4 w1 = Wm1_4[1024 + p];
            float4 w2 = Wm1_4[2048 + p];
            float4 a;
            a.x = c0 * w0.x + c1 * w1.x + c2 * w2.x;
            a.y = c0 * w0.y + c1 * w1.y + c2 * w2.y;
            a.z = c0 * w0.z + c1 * w1.z + c2 * w2.z;
            a.w = c0 * w0.w + c1 * w1.w + c2 * w2.w;
            ((float4*)as)[p] = a;
        }
        // stage f_j natural [node][k]
#pragma unroll
        for (int i = 0; i < 4; i++) {
            int p = i * 256 + tid;
            int r = p >> 4, c4 = p & 15;
            int node = nodeBase + r;
            float4 v = make_float4(0.f, 0.f, 0.f, 0.f);
            if (node < NN) {
                int idx = node * 16 + c4;
                if (j == 0) {
                    v = f0[idx];
                } else if (j == 1) {
                    v = f1[idx];
                } else {
                    float4 a1 = f1[idx], m = msg[idx];
                    float di = dinv_of(node);
                    v.x = a1.x - m.x * di;
                    v.y = a1.y - m.y * di;
                    v.z = a1.z - m.z * di;
                    v.w = a1.w - m.w * di;
                }
            }
            *(float4*)&fs[r * 68 + c4 * 4] = v;
        }
        __syncthreads();
        mma_chunk64(fs, as, tx, ty, acc);
        __syncthreads();
    }

    // bias + relu -> store hf into fs as [node][col], stride 68
    float4 bb = *(const float4*)&bm1[tx * 4];
#pragma unroll
    for (int i = 0; i < 4; i++) {
        int r = ty * 4 + i;
        float4 o;
        o.x = fmaxf(acc[i][0] + bb.x, 0.0f);
        o.y = fmaxf(acc[i][1] + bb.y, 0.0f);
        o.z = fmaxf(acc[i][2] + bb.z, 0.0f);
        o.w = fmaxf(acc[i][3] + bb.w, 0.0f);
        *(float4*)&fs[r * 68 + tx * 4] = o;
    }

    // reset degree counters for the next launch/replay (64 nodes per block)
    if (tid < 64) {
        int node = nodeBase + tid;
        if (node < NN) g_deg[node] = 0;
    }
    __syncthreads();

    // out[n][c] = bm2[c] + sum_k hf[n][k] * Wm2[k][c]
    if (tid < 128) {
        int n = tid >> 1, c = tid & 1;
        int node = nodeBase + n;
        if (node < NN) {
            float s = bm2[c];
#pragma unroll
            for (int k = 0; k < 64; k++) s += fs[n * 68 + k] * wm2s[k * 2 + c];
            out[(size_t)node * 2 + c] = s;
        }
    }
}

// ---------------------------------------------------------------------------
extern "C" void kernel_launch(void* const* d_in, const int* in_sizes, int n_in,
                              void* d_out, int out_size) {
    const float* x = (const float*)d_in[0];
    const void* ei = d_in[1];
    const float* W1 = (const float*)d_in[2];
    const float* b1 = (const float*)d_in[3];
    const float* W2 = (const float*)d_in[4];
    const float* b2 = (const float*)d_in[5];
    const float* Wm1 = (const float*)d_in[6];
    const float* bm1 = (const float*)d_in[7];
    const float* Wm2 = (const float*)d_in[8];
    const float* bm2 = (const float*)d_in[9];
    float* out = (float*)d_out;

    int nbe = (NE + 255) / 256;
    int nb = (NN + 63) / 64;   // 1563
    int nv = (NN * 16 + 255) / 256;
    int ns = (NE * 16) / 256;  // 100000 blocks

    convert_count_kernel<<<nbe, 256>>>(ei);                          // 1
    gemm_relu_kernel<128, false><<<nb, 256>>>(x, -1, W1, b1, 0, -1); // 2
    gemm_relu_kernel<64, true><<<nb, 256>>>(nullptr, 0, W2, b2, 1, 2); // 3
    scatter_kernel<<<ns, 256>>>(2, 3);                               // 4 (profiled)
    update_kernel<<<nv, 256>>>(1, 3, 0, 2);                          // 5
    scatter_kernel<<<ns, 256>>>(2, 3);                               // 6
    final_kernel<<<nb, 256>>>(1, 0, 3, Wm1, bm1, Wm2, bm2, out);     // 7
}